// round 7
// baseline (speedup 1.0000x reference)
#include <cuda_runtime.h>
#include <math.h>

#define HID 64
#define NH 4
#define FD 512
#define NG 128
#define NMAX 50016
#define EMAX 800000
#define FULLM 0xffffffffu

typedef unsigned long long u64;

// ---- scratch (device globals: no allocation allowed) ----
static __device__ float g_fsd[(size_t)NMAX * FD];     // fs | fd  per node
static __device__ float g_hp[(size_t)NMAX * 128];     // per-node: [pair0 64 | pair1 64] head-pair partial outputs (pre-mean, pre-BN)
static __device__ int   g_deg[NMAX];
static __device__ int   g_rowptr[NMAX + 1];
static __device__ int   g_cursor[NMAX];
static __device__ int   g_csrsrc[EMAX];
static __device__ int   g_gptr[NG + 1];
static __device__ float g_bnsum[HID];
static __device__ float g_bnsq[HID];
static __device__ float g_scale[HID];
static __device__ float g_shift[HID];
static __device__ float g_pooled[NG * HID];
static __device__ float g_cat[NG * 3 * HID];
static __device__ float g_tmp[NG * HID];

// ---- tf32 helpers ----
__device__ __forceinline__ void tf32split(float a, unsigned& hi, unsigned& lo) {
    asm("cvt.rna.tf32.f32 %0, %1;" : "=r"(hi) : "f"(a));
    float r = a - __uint_as_float(hi);
    asm("cvt.rna.tf32.f32 %0, %1;" : "=r"(lo) : "f"(r));
}
__device__ __forceinline__ void mma8(float* d, const unsigned* a, unsigned b0, unsigned b1) {
    asm("mma.sync.aligned.m16n8k8.row.col.f32.tf32.tf32.f32 "
        "{%0,%1,%2,%3},{%4,%5,%6,%7},{%8,%9},{%0,%1,%2,%3};"
        : "+f"(d[0]), "+f"(d[1]), "+f"(d[2]), "+f"(d[3])
        : "r"(a[0]), "r"(a[1]), "r"(a[2]), "r"(a[3]), "r"(b0), "r"(b1));
}

// ---- packed f32x2 helpers ----
__device__ __forceinline__ u64 pk2(float lo, float hi) { u64 r; asm("mov.b64 %0,{%1,%2};" : "=l"(r) : "f"(lo), "f"(hi)); return r; }
__device__ __forceinline__ void upk2(u64 v, float& lo, float& hi) { asm("mov.b64 {%0,%1},%2;" : "=f"(lo), "=f"(hi) : "l"(v)); }
__device__ __forceinline__ u64 add2(u64 a, u64 b) { u64 r; asm("add.rn.f32x2 %0,%1,%2;" : "=l"(r) : "l"(a), "l"(b)); return r; }
__device__ __forceinline__ u64 mul2(u64 a, u64 b) { u64 r; asm("mul.rn.f32x2 %0,%1,%2;" : "=l"(r) : "l"(a), "l"(b)); return r; }
__device__ __forceinline__ u64 fma2p(u64 a, u64 b, u64 c) { u64 r; asm("fma.rn.f32x2 %0,%1,%2,%3;" : "=l"(r) : "l"(a), "l"(b), "l"(c)); return r; }

// ============================ GEMM (tensor core, 3xtf32): fsd = bn(h) @ [Wsrc|Wdst] + bias ============================
// mode 0: A = feat (stride 64, raw).  mode 1: A = g_hp (stride 128, combine halves*0.25 + BN affine).
// flags bit1: also histogram dst degrees (layer 0).
__global__ void __launch_bounds__(256) k_gemm(
    const float* __restrict__ A, const float* __restrict__ Ws, const float* __restrict__ Wd,
    const float* __restrict__ bs, const float* __restrict__ bd, int N,
    const int* __restrict__ dstE, int E, int flags)
{
    __shared__ float As[128][68];
    __shared__ float Bh[64][72];
    __shared__ float Bl[64][72];
    int by = blockIdx.y;
    const float* W    = (by < 4) ? Ws : Wd;
    const float* bias = (by < 4) ? bs : bd;
    int cb = (by & 3) * 64;
    int row0 = blockIdx.x * 128;
    int tid = threadIdx.x;

    if (blockIdx.x == 0 && by == 0 && tid < 64) { g_bnsum[tid] = 0.f; g_bnsq[tid] = 0.f; }

    if ((flags & 2) && by == 7) {
        int nbx = gridDim.x;
        int chunk = (E + nbx - 1) / nbx;
        int e0 = blockIdx.x * chunk, e1 = min(e0 + chunk, E);
        for (int e = e0 + tid; e < e1; e += 256) atomicAdd(&g_deg[dstE[e]], 1);
    }

    bool useBN = flags & 1;
    for (int t = tid; t < 2048; t += 256) {     // A: 128x64
        int r = t >> 4, k4 = (t & 15) << 2;
        float4 v = make_float4(0.f, 0.f, 0.f, 0.f);
        if (row0 + r < N) {
            if (!useBN) {
                v = *(const float4*)(A + (size_t)(row0 + r) * 64 + k4);
            } else {
                const float* rp = A + (size_t)(row0 + r) * 128 + k4;
                float4 a = *(const float4*)rp;
                float4 b = *(const float4*)(rp + 64);
                v.x = fmaf(0.25f * (a.x + b.x), g_scale[k4 + 0], g_shift[k4 + 0]);
                v.y = fmaf(0.25f * (a.y + b.y), g_scale[k4 + 1], g_shift[k4 + 1]);
                v.z = fmaf(0.25f * (a.z + b.z), g_scale[k4 + 2], g_shift[k4 + 2]);
                v.w = fmaf(0.25f * (a.w + b.w), g_scale[k4 + 3], g_shift[k4 + 3]);
            }
        }
        *(float4*)&As[r][k4] = v;
    }
    for (int t = tid; t < 1024; t += 256) {     // B: 64x64, pre-split hi/lo
        int k = t >> 4, c4 = (t & 15) << 2;
        float4 v = *(const float4*)(W + (size_t)k * 256 + cb + c4);
        unsigned h0, l0, h1, l1, h2, l2, h3, l3;
        tf32split(v.x, h0, l0); tf32split(v.y, h1, l1);
        tf32split(v.z, h2, l2); tf32split(v.w, h3, l3);
        *(float4*)&Bh[k][c4] = make_float4(__uint_as_float(h0), __uint_as_float(h1), __uint_as_float(h2), __uint_as_float(h3));
        *(float4*)&Bl[k][c4] = make_float4(__uint_as_float(l0), __uint_as_float(l1), __uint_as_float(l2), __uint_as_float(l3));
    }
    __syncthreads();

    int w = tid >> 5, ln = tid & 31;
    int grp = ln >> 2, kq = ln & 3;
    int mrow = w * 16 + grp;

    float acc[8][4];
#pragma unroll
    for (int i = 0; i < 8; i++)
#pragma unroll
        for (int j = 0; j < 4; j++) acc[i][j] = 0.f;

#pragma unroll
    for (int ks = 0; ks < 8; ks++) {
        int kk = ks * 8 + kq;
        unsigned ah[4], al[4];
        tf32split(As[mrow][kk],         ah[0], al[0]);
        tf32split(As[mrow + 8][kk],     ah[1], al[1]);
        tf32split(As[mrow][kk + 4],     ah[2], al[2]);
        tf32split(As[mrow + 8][kk + 4], ah[3], al[3]);
#pragma unroll
        for (int ns = 0; ns < 8; ns++) {
            int c = ns * 8 + grp;
            unsigned bh0 = __float_as_uint(Bh[kk][c]);
            unsigned bh1 = __float_as_uint(Bh[kk + 4][c]);
            unsigned bl0 = __float_as_uint(Bl[kk][c]);
            unsigned bl1 = __float_as_uint(Bl[kk + 4][c]);
            mma8(acc[ns], ah, bh0, bh1);
            mma8(acc[ns], ah, bl0, bl1);
            mma8(acc[ns], al, bh0, bh1);
        }
    }

    int r0 = row0 + w * 16 + grp;
#pragma unroll
    for (int ns = 0; ns < 8; ns++) {
        int lc = ns * 8 + 2 * kq;
        float b0 = __ldg(bias + cb + lc), b1 = __ldg(bias + cb + lc + 1);
        if (r0 < N) {
            *(float2*)(g_fsd + (size_t)r0 * FD + by * 64 + lc) = make_float2(acc[ns][0] + b0, acc[ns][1] + b1);
        }
        if (r0 + 8 < N) {
            *(float2*)(g_fsd + (size_t)(r0 + 8) * FD + by * 64 + lc) = make_float2(acc[ns][2] + b0, acc[ns][3] + b1);
        }
    }
}

// ============================ single-block scan: rowptr/cursor from deg ============================
__global__ void __launch_bounds__(1024) k_scan(int n, int E) {
    __shared__ int sh[1024];
    int t = threadIdx.x;
    int per = (n + 1023) >> 10;
    int b0 = t * per, b1 = min(b0 + per, n);
    int s = 0;
    for (int i = b0; i < b1; i++) s += g_deg[i];
    sh[t] = s;
    __syncthreads();
    for (int off = 1; off < 1024; off <<= 1) {
        int v = (t >= off) ? sh[t - off] : 0;
        __syncthreads();
        sh[t] += v;
        __syncthreads();
    }
    int run = sh[t] - s;
    for (int i = b0; i < b1; i++) {
        g_rowptr[i] = run;
        g_cursor[i] = run;
        run += g_deg[i];
    }
    if (t == 0) g_rowptr[n] = E;
}

__global__ void k_scatter(const int* __restrict__ src, const int* __restrict__ dst, int E) {
    int i = blockIdx.x * blockDim.x + threadIdx.x;
    if (i < E) {
        int p = atomicAdd(&g_cursor[dst[i]], 1);
        g_csrsrc[p] = src[i];
    }
}

__global__ void k_gptr(const int* __restrict__ gid, int N) {
    int i = blockIdx.x * 256 + threadIdx.x;
    if (i < N) {
        int g = gid[i];
        int gp = (i == 0) ? -1 : gid[i - 1];
        for (int gg = gp + 1; gg <= g; gg++) g_gptr[gg] = i;
        if (i == N - 1) for (int gg = g + 1; gg <= NG; gg++) g_gptr[gg] = N;
    }
}

// ============================ Edge aggregation: head-pair split, 4-deep prefetch, no-max softmax ============================
// One warp per (node, head-pair). Lane covers 4 dims: foff = pair*128 + lane*4.
// Lanes 0-15 = head 2p (local dims lane*4..), lanes 16-31 = head 2p+1.
#define AGG_ABS 0x7fffffff7fffffffULL

#define AGG_PF(buf, idx) do { int _i = (idx); if (_i < end) { \
    int _q = _i - p0; \
    if (_q == 32) { p0 += 32; mysrc = (p0 + lane < end) ? g_csrsrc[p0 + lane] : 0; _q = 0; } \
    int _s = __shfl_sync(FULLM, mysrc, _q); \
    ulonglong2 _a = *(const ulonglong2*)(g_fsd + (size_t)_s * FD + foff); \
    buf[0] = _a.x; buf[1] = _a.y; } } while (0)

#define AGG_PROC(buf, idx) do { if ((idx) < end) { \
    u64 _e0 = add2(buf[0], fdv[0]), _e1 = add2(buf[1], fdv[1]); \
    u64 _u0 = fma2p(_e0 & AGG_ABS, C04, mul2(_e0, C06)); \
    u64 _u1 = fma2p(_e1 & AGG_ABS, C04, mul2(_e1, C06)); \
    u64 _p2 = fma2p(av[1], _u1, mul2(av[0], _u0)); \
    float _lo, _hi; upk2(_p2, _lo, _hi); \
    float _pt = _lo + _hi; \
    _pt += __shfl_xor_sync(FULLM, _pt, 1); \
    _pt += __shfl_xor_sync(FULLM, _pt, 2); \
    _pt += __shfl_xor_sync(FULLM, _pt, 4); \
    _pt += __shfl_xor_sync(FULLM, _pt, 8); \
    float _w = __expf(_pt); \
    s += _w; \
    u64 _w2 = pk2(_w, _w); \
    acc[0] = fma2p(_w2, buf[0], acc[0]); \
    acc[1] = fma2p(_w2, buf[1], acc[1]); } } while (0)

__global__ void __launch_bounds__(256, 5) k_aggr(const float* __restrict__ attn_i, int N)
{
    int tid = threadIdx.x;
    int lane = tid & 31, warp = tid >> 5;
    int node = blockIdx.x * 4 + (warp >> 1);
    int pair = warp & 1;
    if (node >= N) return;           // warp-uniform

    const int foff = pair * 128 + lane * 4;
    const u64 C06 = pk2(0.6f, 0.6f);
    const u64 C04 = pk2(0.4f, 0.4f);

    u64 fdv[2], av[2];
    {
        ulonglong2 a = *(const ulonglong2*)(g_fsd + (size_t)node * FD + 256 + foff);
        fdv[0] = a.x; fdv[1] = a.y;
        ulonglong2 c = *(const ulonglong2*)(attn_i + foff);
        av[0] = c.x; av[1] = c.y;
    }

    float s = 0.f;
    u64 acc[2] = {0ull, 0ull};
    int beg = g_rowptr[node], end = g_rowptr[node + 1];

    if (beg < end) {
        int p0 = beg;
        int mysrc = (beg + lane < end) ? g_csrsrc[beg + lane] : 0;
        u64 f0[2], f1[2], f2[2], f3[2];
        AGG_PF(f0, beg);
        AGG_PF(f1, beg + 1);
        AGG_PF(f2, beg + 2);
        for (int p = beg; p < end; p += 4) {
            AGG_PF(f3, p + 3);  AGG_PROC(f0, p);
            AGG_PF(f0, p + 4);  AGG_PROC(f1, p + 1);
            AGG_PF(f1, p + 5);  AGG_PROC(f2, p + 2);
            AGG_PF(f2, p + 6);  AGG_PROC(f3, p + 3);
        }
    }

    float inv = (end > beg) ? 1.f / s : 0.f;
    float v0, v1, v2, v3;
    upk2(acc[0], v0, v1);
    upk2(acc[1], v2, v3);
    v0 = fmaxf(v0 * inv, 0.f); v1 = fmaxf(v1 * inv, 0.f);
    v2 = fmaxf(v2 * inv, 0.f); v3 = fmaxf(v3 * inv, 0.f);
    v0 += __shfl_xor_sync(FULLM, v0, 16);      // sum the pair's two heads
    v1 += __shfl_xor_sync(FULLM, v1, 16);
    v2 += __shfl_xor_sync(FULLM, v2, 16);
    v3 += __shfl_xor_sync(FULLM, v3, 16);
    if (lane < 16) {
        *(float4*)(g_hp + (size_t)node * 128 + pair * 64 + lane * 4) = make_float4(v0, v1, v2, v3);
    }
}

// ============================ SumPooling + BN statistics (raw, pre-BN) ============================
__global__ void __launch_bounds__(256) k_pool() {
    int g = blockIdx.x;
    int tid = threadIdx.x;
    int beg = g_gptr[g], end = g_gptr[g + 1];
    int c = tid & 63;
    float S = 0.f, Q = 0.f;
    for (int n = beg + (tid >> 6); n < end; n += 4) {
        float h = 0.25f * (g_hp[(size_t)n * 128 + c] + g_hp[(size_t)n * 128 + 64 + c]);
        S += h;
        Q += h * h;
    }
    __shared__ float r1[256], r2[256];
    r1[tid] = S; r2[tid] = Q;
    __syncthreads();
    if (tid < 128) { r1[tid] += r1[tid + 128]; r2[tid] += r2[tid + 128]; }
    __syncthreads();
    if (tid < 64) {
        float St = r1[tid] + r1[tid + 64];
        float Qt = r2[tid] + r2[tid + 64];
        g_pooled[g * 64 + tid] = St;                  // RAW pooled sum (pre-BN)
        atomicAdd(&g_bnsum[tid], St);
        atomicAdd(&g_bnsq[tid], Qt);
    }
}

// ============================ BN finalize + apply affine to pooled (pooling is linear) ============================
__global__ void __launch_bounds__(256) k_bnfin(const float* __restrict__ g, const float* __restrict__ b, float invN) {
    __shared__ float ssc[64], ssh[64];
    int tid = threadIdx.x;
    if (tid < 64) {
        float mu = g_bnsum[tid] * invN;
        float var = g_bnsq[tid] * invN - mu * mu;
        float sc = g[tid] * rsqrtf(var + 1e-5f);
        float sh = b[tid] - mu * sc;
        g_scale[tid] = sc; g_shift[tid] = sh;
        ssc[tid] = sc; ssh[tid] = sh;
    }
    __syncthreads();
    for (int t = tid; t < NG * 64; t += 256) {
        int gr = t >> 6, c = t & 63;
        float cnt = (float)(g_gptr[gr + 1] - g_gptr[gr]);
        g_pooled[t] = ssc[c] * g_pooled[t] + cnt * ssh[c];
    }
}

// ============================ per-layer pooled MLP ============================
__global__ void __launch_bounds__(512) k_poolmlp(
    const float* __restrict__ W, const float* __restrict__ b,
    const float* __restrict__ g, const float* __restrict__ bt, int layer)
{
    __shared__ float sw[64 * 64];
    __shared__ float psum[8][64], psq[8][64];
    __shared__ float sscale[64], sshift[64];
    int tid = threadIdx.x;
    for (int t = tid; t < 4096; t += 512) sw[t] = W[t];
    __syncthreads();
    int c = tid & 63, gs = tid >> 6;
    float vals[16];
    float lsum = 0.f, lsq = 0.f;
    for (int gg = 0; gg < 16; gg++) {
        int gr = gs * 16 + gg;
        float a = b[c];
#pragma unroll
        for (int k = 0; k < 64; k++) a = fmaf(g_pooled[gr * 64 + k], sw[k * 64 + c], a);
        a = fmaxf(a, 0.f);
        vals[gg] = a;
        lsum += a;
        lsq += a * a;
    }
    psum[gs][c] = lsum;
    psq[gs][c]  = lsq;
    __syncthreads();
    if (tid < 64) {
        float S = 0.f, Q = 0.f;
        for (int k = 0; k < 8; k++) { S += psum[k][tid]; Q += psq[k][tid]; }
        float mu = S * (1.f / 128.f), var = Q * (1.f / 128.f) - mu * mu;
        float sc = g[tid] * rsqrtf(var + 1e-5f);
        sscale[tid] = sc;
        sshift[tid] = bt[tid] - mu * sc;
    }
    __syncthreads();
    for (int gg = 0; gg < 16; gg++) {
        int gr = gs * 16 + gg;
        g_cat[gr * 192 + layer * 64 + c] = vals[gg] * sscale[c] + sshift[c];
    }
}

// ============================ head ============================
__global__ void k_final1(const float* __restrict__ W, const float* __restrict__ b) {
    int gr = blockIdx.x, c = threadIdx.x;
    __shared__ float srow[192];
    for (int t = c; t < 192; t += 64) srow[t] = g_cat[gr * 192 + t];
    __syncthreads();
    float a = b[c];
    for (int k = 0; k < 192; k++) a = fmaf(srow[k], W[k * 64 + c], a);
    g_tmp[gr * 64 + c] = fmaxf(a, 0.f);
}

__global__ void __launch_bounds__(128) k_final2(
    const float* __restrict__ blg, const float* __restrict__ blbt,
    const float* __restrict__ llW, const float* __restrict__ llb,
    const float* __restrict__ llg, const float* __restrict__ llbt,
    float* out_lg, float* out_hh)
{
    __shared__ float st[128 * 64];
    __shared__ float o2[128 * 10];
    __shared__ float sc1[64], sh1[64], sc2[10], sh2[10];
    int tid = threadIdx.x;
    for (int t = tid; t < 8192; t += 128) st[t] = g_tmp[t];
    __syncthreads();
    if (tid < 64) {
        float S = 0.f, Q = 0.f;
        for (int gr = 0; gr < 128; gr++) { float v = st[gr * 64 + tid]; S += v; Q += v * v; }
        float mu = S * (1.f / 128.f), var = Q * (1.f / 128.f) - mu * mu;
        float sc = blg[tid] * rsqrtf(var + 1e-5f);
        sc1[tid] = sc;
        sh1[tid] = blbt[tid] - mu * sc;
    }
    __syncthreads();
    for (int t = tid; t < 8192; t += 128) {
        int c = t & 63;
        st[t] = st[t] * sc1[c] + sh1[c];
    }
    __syncthreads();
    if (out_hh) for (int t = tid; t < 8192; t += 128) out_hh[t] = st[t];

    for (int t = tid; t < 1280; t += 128) {
        int gr = t / 10, j = t % 10;
        float a = llb[j];
#pragma unroll
        for (int k = 0; k < 64; k++) a = fmaf(st[gr * 64 + k], llW[k * 10 + j], a);
        o2[t] = fmaxf(a, 0.f);
    }
    __syncthreads();
    if (tid < 10) {
        float S = 0.f, Q = 0.f;
        for (int gr = 0; gr < 128; gr++) { float v = o2[gr * 10 + tid]; S += v; Q += v * v; }
        float mu = S * (1.f / 128.f), var = Q * (1.f / 128.f) - mu * mu;
        float sc = llg[tid] * rsqrtf(var + 1e-5f);
        sc2[tid] = sc;
        sh2[tid] = llbt[tid] - mu * sc;
    }
    __syncthreads();
    if (tid < 128 && out_lg) {
        float y[10];
        float mx = __int_as_float(0xff800000);
        for (int j = 0; j < 10; j++) {
            y[j] = o2[tid * 10 + j] * sc2[j] + sh2[j];
            mx = fmaxf(mx, y[j]);
        }
        float se = 0.f;
        for (int j = 0; j < 10; j++) se += expf(y[j] - mx);
        float lse = mx + logf(se);
        for (int j = 0; j < 10; j++) out_lg[tid * 10 + j] = y[j] - lse;
    }
}

// ============================ host ============================
extern "C" void kernel_launch(void* const* d_in, const int* in_sizes, int n_in,
                              void* d_out, int out_size)
{
    const float* feat = (const float*)d_in[0];
    const float* Wsrc = (const float*)d_in[1];
    const float* bsrc = (const float*)d_in[2];
    const float* Wdst = (const float*)d_in[3];
    const float* bdst = (const float*)d_in[4];
    const float* attn = (const float*)d_in[5];
    const float* bng  = (const float*)d_in[6];
    const float* bnb  = (const float*)d_in[7];
    const float* lpW  = (const float*)d_in[8];
    const float* lpb  = (const float*)d_in[9];
    const float* lpg  = (const float*)d_in[10];
    const float* lpbt = (const float*)d_in[11];
    const float* blW  = (const float*)d_in[12];
    const float* blb  = (const float*)d_in[13];
    const float* blg  = (const float*)d_in[14];
    const float* blbt = (const float*)d_in[15];
    const float* llW  = (const float*)d_in[16];
    const float* llb  = (const float*)d_in[17];
    const float* llg  = (const float*)d_in[18];
    const float* llbt = (const float*)d_in[19];
    const int* src = (const int*)d_in[20];
    const int* dst = (const int*)d_in[21];
    const int* gid = (const int*)d_in[22];

    int N = in_sizes[0] / 64;
    int E = in_sizes[20];

    void* p;
    cudaGetSymbolAddress(&p, g_hp);
    const float* hp_p = (const float*)p;
    cudaGetSymbolAddress(&p, g_deg);
    int* deg_p = (int*)p;

    cudaMemsetAsync(deg_p, 0, N * sizeof(int));

    dim3 gg((N + 127) / 128, 8);
    int aggrGrid = (N + 3) / 4;

    // my launch idx: 0 gemm(L0,+hist), 1 scan, 2 scatter, 3 aggr(L0) <-- profiled
    k_gemm<<<gg, 256>>>(feat, Wsrc, Wdst, bsrc, bdst, N, dst, E, 2);
    k_scan<<<1, 1024>>>(N, E);
    k_scatter<<<(E + 255) / 256, 256>>>(src, dst, E);
    k_aggr<<<aggrGrid, 256>>>(attn, N);

    k_gptr<<<(N + 255) / 256, 256>>>(gid, N);
    k_pool<<<NG, 256>>>();
    k_bnfin<<<1, 256>>>(bng, bnb, 1.0f / (float)N);
    k_poolmlp<<<1, 512>>>(lpW, lpb, lpg, lpbt, 0);

    for (int i = 1; i < 3; i++) {
        k_gemm<<<gg, 256>>>(hp_p, Wsrc + (size_t)i * 64 * 256, Wdst + (size_t)i * 64 * 256,
                            bsrc + i * 256, bdst + i * 256, N, dst, E, 1);
        k_aggr<<<aggrGrid, 256>>>(attn + i * 256, N);
        k_pool<<<NG, 256>>>();
        k_bnfin<<<1, 256>>>(bng + i * 64, bnb + i * 64, 1.0f / (float)N);
        k_poolmlp<<<1, 512>>>(lpW + (size_t)i * 64 * 64, lpb + i * 64, lpg + i * 64, lpbt + i * 64, i);
    }

    k_final1<<<128, 64>>>(blW, blb);

    float* out = (float*)d_out;
    float* out_lg = nullptr;
    float* out_hh = nullptr;
    if (out_size >= 9472)      { out_lg = out; out_hh = out + 1280; }
    else if (out_size == 1280) { out_lg = out; }
    else                       { out_hh = out; }
    k_final2<<<1, 128>>>(blg, blbt, llW, llb, llg, llbt, out_lg, out_hh);
}

// round 8
// speedup vs baseline: 1.2890x; 1.2890x over previous
#include <cuda_runtime.h>
#include <math.h>

#define HID 64
#define NH 4
#define FD 512
#define NG 128
#define NMAX 50016
#define EMAX 800000
#define FULLM 0xffffffffu

typedef unsigned long long u64;

// ---- scratch (device globals: no allocation allowed) ----
static __device__ float g_fsd[(size_t)NMAX * FD];     // fs | fd  per node
static __device__ float g_hpre[NMAX * HID];           // layer output pre-BN
static __device__ int   g_deg[NMAX];
static __device__ int   g_rowptr[NMAX + 1];
static __device__ int   g_cursor[NMAX];
static __device__ int   g_csrsrc[EMAX];
static __device__ int   g_part[64];
static __device__ int   g_gptr[NG + 1];
static __device__ float g_bnsum[HID];
static __device__ float g_bnsq[HID];
static __device__ float g_scale[HID];
static __device__ float g_shift[HID];
static __device__ float g_pooled[NG * HID];
static __device__ float g_cat[NG * 3 * HID];
static __device__ float g_tmp[NG * HID];

// ---- tf32 helpers ----
__device__ __forceinline__ void tf32split(float a, unsigned& hi, unsigned& lo) {
    asm("cvt.rna.tf32.f32 %0, %1;" : "=r"(hi) : "f"(a));
    float r = a - __uint_as_float(hi);
    asm("cvt.rna.tf32.f32 %0, %1;" : "=r"(lo) : "f"(r));
}
__device__ __forceinline__ void mma8(float* d, const unsigned* a, unsigned b0, unsigned b1) {
    asm("mma.sync.aligned.m16n8k8.row.col.f32.tf32.tf32.f32 "
        "{%0,%1,%2,%3},{%4,%5,%6,%7},{%8,%9},{%0,%1,%2,%3};"
        : "+f"(d[0]), "+f"(d[1]), "+f"(d[2]), "+f"(d[3])
        : "r"(a[0]), "r"(a[1]), "r"(a[2]), "r"(a[3]), "r"(b0), "r"(b1));
}

// ---- packed f32x2 helpers ----
__device__ __forceinline__ u64 pk2(float lo, float hi) { u64 r; asm("mov.b64 %0,{%1,%2};" : "=l"(r) : "f"(lo), "f"(hi)); return r; }
__device__ __forceinline__ void upk2(u64 v, float& lo, float& hi) { asm("mov.b64 {%0,%1},%2;" : "=f"(lo), "=f"(hi) : "l"(v)); }
__device__ __forceinline__ u64 add2(u64 a, u64 b) { u64 r; asm("add.rn.f32x2 %0,%1,%2;" : "=l"(r) : "l"(a), "l"(b)); return r; }
__device__ __forceinline__ u64 mul2(u64 a, u64 b) { u64 r; asm("mul.rn.f32x2 %0,%1,%2;" : "=l"(r) : "l"(a), "l"(b)); return r; }
__device__ __forceinline__ u64 fma2p(u64 a, u64 b, u64 c) { u64 r; asm("fma.rn.f32x2 %0,%1,%2,%3;" : "=l"(r) : "l"(a), "l"(b), "l"(c)); return r; }

// ============================ GEMM (tensor core, 3xtf32): fsd = bn(h) @ [Wsrc|Wdst] + bias ============================
// 3 CTA/SM forced: smem 71.7KB*3=215KB<228KB, regs capped at 84 by launch_bounds.
__global__ void __launch_bounds__(256, 3) k_gemm(
    const float* __restrict__ A, const float* __restrict__ Ws, const float* __restrict__ Wd,
    const float* __restrict__ bs, const float* __restrict__ bd, int N, int useBN)
{
    __shared__ float As[128][68];     // pad 68 -> bank(4m+k), conflict-free frags
    __shared__ float Bh[64][72];      // tf32-hi bits
    __shared__ float Bl[64][72];      // tf32-lo bits
    int by = blockIdx.y;
    const float* W    = (by < 4) ? Ws : Wd;
    const float* bias = (by < 4) ? bs : bd;
    int cb = (by & 3) * 64;
    int row0 = blockIdx.x * 128;
    int tid = threadIdx.x;

    if (blockIdx.x == 0 && by == 0 && tid < 64) { g_bnsum[tid] = 0.f; g_bnsq[tid] = 0.f; }

    for (int t = tid; t < 2048; t += 256) {     // A: 128x64
        int r = t >> 4, k4 = (t & 15) << 2;
        float4 v = make_float4(0.f, 0.f, 0.f, 0.f);
        if (row0 + r < N) v = *(const float4*)(A + (size_t)(row0 + r) * 64 + k4);
        if (useBN) {
            v.x = fmaf(v.x, g_scale[k4 + 0], g_shift[k4 + 0]);
            v.y = fmaf(v.y, g_scale[k4 + 1], g_shift[k4 + 1]);
            v.z = fmaf(v.z, g_scale[k4 + 2], g_shift[k4 + 2]);
            v.w = fmaf(v.w, g_scale[k4 + 3], g_shift[k4 + 3]);
        }
        *(float4*)&As[r][k4] = v;
    }
    for (int t = tid; t < 1024; t += 256) {     // B: 64x64, pre-split hi/lo
        int k = t >> 4, c4 = (t & 15) << 2;
        float4 v = *(const float4*)(W + (size_t)k * 256 + cb + c4);
        unsigned h0, l0, h1, l1, h2, l2, h3, l3;
        tf32split(v.x, h0, l0); tf32split(v.y, h1, l1);
        tf32split(v.z, h2, l2); tf32split(v.w, h3, l3);
        *(float4*)&Bh[k][c4] = make_float4(__uint_as_float(h0), __uint_as_float(h1), __uint_as_float(h2), __uint_as_float(h3));
        *(float4*)&Bl[k][c4] = make_float4(__uint_as_float(l0), __uint_as_float(l1), __uint_as_float(l2), __uint_as_float(l3));
    }
    __syncthreads();

    int w = tid >> 5, ln = tid & 31;
    int grp = ln >> 2, kq = ln & 3;
    int mrow = w * 16 + grp;

    float acc[8][4];
#pragma unroll
    for (int i = 0; i < 8; i++)
#pragma unroll
        for (int j = 0; j < 4; j++) acc[i][j] = 0.f;

#pragma unroll
    for (int ks = 0; ks < 8; ks++) {
        int kk = ks * 8 + kq;
        unsigned ah[4], al[4];
        tf32split(As[mrow][kk],         ah[0], al[0]);
        tf32split(As[mrow + 8][kk],     ah[1], al[1]);
        tf32split(As[mrow][kk + 4],     ah[2], al[2]);
        tf32split(As[mrow + 8][kk + 4], ah[3], al[3]);
#pragma unroll
        for (int ns = 0; ns < 8; ns++) {
            int c = ns * 8 + grp;
            unsigned bh0 = __float_as_uint(Bh[kk][c]);
            unsigned bh1 = __float_as_uint(Bh[kk + 4][c]);
            unsigned bl0 = __float_as_uint(Bl[kk][c]);
            unsigned bl1 = __float_as_uint(Bl[kk + 4][c]);
            mma8(acc[ns], ah, bh0, bh1);
            mma8(acc[ns], ah, bl0, bl1);
            mma8(acc[ns], al, bh0, bh1);
        }
    }

    int r0 = row0 + w * 16 + grp;
#pragma unroll
    for (int ns = 0; ns < 8; ns++) {
        int lc = ns * 8 + 2 * kq;
        float b0 = __ldg(bias + cb + lc), b1 = __ldg(bias + cb + lc + 1);
        if (r0 < N) {
            *(float2*)(g_fsd + (size_t)r0 * FD + by * 64 + lc) = make_float2(acc[ns][0] + b0, acc[ns][1] + b1);
        }
        if (r0 + 8 < N) {
            *(float2*)(g_fsd + (size_t)(r0 + 8) * FD + by * 64 + lc) = make_float2(acc[ns][2] + b0, acc[ns][3] + b1);
        }
    }
}

// ============================ CSR build (R4 two-level scan) ============================
__global__ void k_hist(const int* __restrict__ dst, int E) {
    int i = blockIdx.x * blockDim.x + threadIdx.x;
    if (i < E) atomicAdd(&g_deg[dst[i]], 1);
}

__global__ void k_scan1(int n) {
    __shared__ int s[1024];
    int tid = threadIdx.x;
    int i = blockIdx.x * 1024 + tid;
    int v = (i < n) ? g_deg[i] : 0;
    s[tid] = v;
    __syncthreads();
    for (int off = 1; off < 1024; off <<= 1) {
        int t = (tid >= off) ? s[tid - off] : 0;
        __syncthreads();
        s[tid] += t;
        __syncthreads();
    }
    if (i < n) g_rowptr[i] = s[tid] - v;
    if (tid == 1023) g_part[blockIdx.x] = s[1023];
}

__global__ void k_scan23(int n, int E, int nb) {
    __shared__ int s[64];
    int tid = threadIdx.x;
    if (tid < 64) s[tid] = (tid < nb) ? g_part[tid] : 0;
    __syncthreads();
    if (tid == 0) {
        int run = 0;
        for (int k = 0; k < 64; k++) { int v = s[k]; s[k] = run; run += v; }
    }
    __syncthreads();
    int i = blockIdx.x * 1024 + tid;
    if (i < n) {
        int r = g_rowptr[i] + s[blockIdx.x];
        g_rowptr[i] = r;
        g_cursor[i] = r;
    }
    if (blockIdx.x == 0 && tid == 0) g_rowptr[n] = E;
}

__global__ void k_scatter(const int* __restrict__ src, const int* __restrict__ dst, int E) {
    int i = blockIdx.x * blockDim.x + threadIdx.x;
    if (i < E) {
        int p = atomicAdd(&g_cursor[dst[i]], 1);
        g_csrsrc[p] = src[i];
    }
}

__global__ void k_gptr(const int* __restrict__ gid, int N) {
    int i = blockIdx.x * 256 + threadIdx.x;
    if (i < N) {
        int g = gid[i];
        int gp = (i == 0) ? -1 : gid[i - 1];
        for (int gg = gp + 1; gg <= g; gg++) g_gptr[gg] = i;
        if (i == N - 1) for (int gg = g + 1; gg <= NG; gg++) g_gptr[gg] = N;
    }
}

// ============================ Edge aggregation: packed f32x2, no-max softmax, unroll-2 prefetch ============================
// One warp per node; lane covers dims [l*8, l*8+8). leaky(e) = 0.6e + 0.4|e|.
__device__ __forceinline__ void loadp4(u64* f, int src, int lane) {
    const ulonglong2* fp = (const ulonglong2*)(g_fsd + (size_t)src * FD + lane * 8);
    ulonglong2 a = fp[0], b = fp[1];
    f[0] = a.x; f[1] = a.y; f[2] = b.x; f[3] = b.y;
}
__device__ __forceinline__ float logitp(const u64* fv, const u64* fdv, const u64* av, u64 C06, u64 C04) {
    u64 part2 = 0ull;
#pragma unroll
    for (int j = 0; j < 4; j++) {
        u64 e = add2(fv[j], fdv[j]);
        u64 ae = e & 0x7fffffff7fffffffULL;
        u64 u = fma2p(ae, C04, mul2(e, C06));
        part2 = fma2p(av[j], u, part2);
    }
    float lo, hi;
    upk2(part2, lo, hi);
    float part = lo + hi;
    part += __shfl_xor_sync(FULLM, part, 1);
    part += __shfl_xor_sync(FULLM, part, 2);
    part += __shfl_xor_sync(FULLM, part, 4);
    return part;
}

__global__ void __launch_bounds__(256, 4) k_aggr(const float* __restrict__ attn_i, int N)
{
    int tid = threadIdx.x;
    int lane = tid & 31, warp = tid >> 5;
    int node = blockIdx.x * 8 + warp;
    if (node >= N) return;     // warp-uniform

    const u64 C06 = pk2(0.6f, 0.6f);
    const u64 C04 = pk2(0.4f, 0.4f);

    u64 fdv[4], av[4];
    {
        const ulonglong2* fdp = (const ulonglong2*)(g_fsd + (size_t)node * FD + 256 + lane * 8);
        ulonglong2 a = fdp[0], b = fdp[1];
        fdv[0] = a.x; fdv[1] = a.y; fdv[2] = b.x; fdv[3] = b.y;
        const ulonglong2* ap = (const ulonglong2*)(attn_i + lane * 8);
        ulonglong2 c = ap[0], d = ap[1];
        av[0] = c.x; av[1] = c.y; av[2] = d.x; av[3] = d.y;
    }

    float s = 0.f;
    u64 acc[4] = {0ull, 0ull, 0ull, 0ull};
    int beg = g_rowptr[node], end = g_rowptr[node + 1];

    if (beg < end) {
        int p0 = beg;
        int mysrc = (beg + lane < end) ? g_csrsrc[beg + lane] : 0;
        u64 fA[4], fB[4];
        {
            int s0 = __shfl_sync(FULLM, mysrc, 0);
            loadp4(fA, s0, lane);
        }
        for (int p = beg; p < end; p += 2) {
            if (p + 1 < end) {                 // prefetch edge p+1 into fB
                int q = p + 1 - p0;
                if (q == 32) { p0 += 32; mysrc = (p0 + lane < end) ? g_csrsrc[p0 + lane] : 0; q = 0; }
                int s1 = __shfl_sync(FULLM, mysrc, q);
                loadp4(fB, s1, lane);
            }
            {   // process edge p from fA
                float w = __expf(logitp(fA, fdv, av, C06, C04));
                s += w;
                u64 w2 = pk2(w, w);
#pragma unroll
                for (int j = 0; j < 4; j++) acc[j] = fma2p(w2, fA[j], acc[j]);
            }
            if (p + 1 < end) {
                if (p + 2 < end) {             // prefetch edge p+2 into fA
                    int q = p + 2 - p0;
                    if (q == 32) { p0 += 32; mysrc = (p0 + lane < end) ? g_csrsrc[p0 + lane] : 0; q = 0; }
                    int s2 = __shfl_sync(FULLM, mysrc, q);
                    loadp4(fA, s2, lane);
                }
                float w = __expf(logitp(fB, fdv, av, C06, C04));
                s += w;
                u64 w2 = pk2(w, w);
#pragma unroll
                for (int j = 0; j < 4; j++) acc[j] = fma2p(w2, fB[j], acc[j]);
            }
        }
    }
    float inv = (end > beg) ? 1.f / s : 0.f;
    float o[8];
#pragma unroll
    for (int j = 0; j < 4; j++) {
        float lo, hi;
        upk2(acc[j], lo, hi);
        float v0 = fmaxf(lo * inv, 0.f);
        float v1 = fmaxf(hi * inv, 0.f);
        v0 += __shfl_xor_sync(FULLM, v0, 8);
        v0 += __shfl_xor_sync(FULLM, v0, 16);
        v1 += __shfl_xor_sync(FULLM, v1, 8);
        v1 += __shfl_xor_sync(FULLM, v1, 16);
        o[2 * j]     = v0 * 0.25f;
        o[2 * j + 1] = v1 * 0.25f;
    }
    if (lane < 8) {
        float* hp = g_hpre + (size_t)node * HID + lane * 8;
        *(float4*)hp       = make_float4(o[0], o[1], o[2], o[3]);
        *(float4*)(hp + 4) = make_float4(o[4], o[5], o[6], o[7]);
    }
}

// ============================ SumPooling + BN statistics (raw, pre-BN) ============================
__global__ void __launch_bounds__(256) k_pool() {
    int g = blockIdx.x;
    int tid = threadIdx.x;
    int beg = g_gptr[g], end = g_gptr[g + 1];
    int c = tid & 63;
    float S = 0.f, Q = 0.f;
    for (int n = beg + (tid >> 6); n < end; n += 4) {
        float h = g_hpre[(size_t)n * 64 + c];
        S += h;
        Q += h * h;
    }
    __shared__ float r1[256], r2[256];
    r1[tid] = S; r2[tid] = Q;
    __syncthreads();
    if (tid < 128) { r1[tid] += r1[tid + 128]; r2[tid] += r2[tid + 128]; }
    __syncthreads();
    if (tid < 64) {
        float St = r1[tid] + r1[tid + 64];
        float Qt = r2[tid] + r2[tid + 64];
        g_pooled[g * 64 + tid] = St;                  // RAW pooled sum (pre-BN)
        atomicAdd(&g_bnsum[tid], St);
        atomicAdd(&g_bnsq[tid], Qt);
    }
}

// ============================ BN finalize + apply affine to pooled (pooling is linear) ============================
__global__ void __launch_bounds__(256) k_bnfin(const float* __restrict__ g, const float* __restrict__ b, float invN) {
    __shared__ float ssc[64], ssh[64];
    int tid = threadIdx.x;
    if (tid < 64) {
        float mu = g_bnsum[tid] * invN;
        float var = g_bnsq[tid] * invN - mu * mu;
        float sc = g[tid] * rsqrtf(var + 1e-5f);
        float sh = b[tid] - mu * sc;
        g_scale[tid] = sc; g_shift[tid] = sh;
        ssc[tid] = sc; ssh[tid] = sh;
    }
    __syncthreads();
    for (int t = tid; t < NG * 64; t += 256) {
        int gr = t >> 6, c = t & 63;
        float cnt = (float)(g_gptr[gr + 1] - g_gptr[gr]);
        g_pooled[t] = ssc[c] * g_pooled[t] + cnt * ssh[c];
    }
}

// ============================ per-layer pooled MLP ============================
__global__ void __launch_bounds__(512) k_poolmlp(
    const float* __restrict__ W, const float* __restrict__ b,
    const float* __restrict__ g, const float* __restrict__ bt, int layer)
{
    __shared__ float sw[64 * 64];
    __shared__ float psum[8][64], psq[8][64];
    __shared__ float sscale[64], sshift[64];
    int tid = threadIdx.x;
    for (int t = tid; t < 4096; t += 512) sw[t] = W[t];
    __syncthreads();
    int c = tid & 63, gs = tid >> 6;
    float vals[16];
    float lsum = 0.f, lsq = 0.f;
    for (int gg = 0; gg < 16; gg++) {
        int gr = gs * 16 + gg;
        float a = b[c];
#pragma unroll
        for (int k = 0; k < 64; k++) a = fmaf(g_pooled[gr * 64 + k], sw[k * 64 + c], a);
        a = fmaxf(a, 0.f);
        vals[gg] = a;
        lsum += a;
        lsq += a * a;
    }
    psum[gs][c] = lsum;
    psq[gs][c]  = lsq;
    __syncthreads();
    if (tid < 64) {
        float S = 0.f, Q = 0.f;
        for (int k = 0; k < 8; k++) { S += psum[k][tid]; Q += psq[k][tid]; }
        float mu = S * (1.f / 128.f), var = Q * (1.f / 128.f) - mu * mu;
        float sc = g[tid] * rsqrtf(var + 1e-5f);
        sscale[tid] = sc;
        sshift[tid] = bt[tid] - mu * sc;
    }
    __syncthreads();
    for (int gg = 0; gg < 16; gg++) {
        int gr = gs * 16 + gg;
        g_cat[gr * 192 + layer * 64 + c] = vals[gg] * sscale[c] + sshift[c];
    }
}

// ============================ head ============================
__global__ void k_final1(const float* __restrict__ W, const float* __restrict__ b) {
    int gr = blockIdx.x, c = threadIdx.x;
    __shared__ float srow[192];
    for (int t = c; t < 192; t += 64) srow[t] = g_cat[gr * 192 + t];
    __syncthreads();
    float a = b[c];
    for (int k = 0; k < 192; k++) a = fmaf(srow[k], W[k * 64 + c], a);
    g_tmp[gr * 64 + c] = fmaxf(a, 0.f);
}

__global__ void __launch_bounds__(128) k_final2(
    const float* __restrict__ blg, const float* __restrict__ blbt,
    const float* __restrict__ llW, const float* __restrict__ llb,
    const float* __restrict__ llg, const float* __restrict__ llbt,
    float* out_lg, float* out_hh)
{
    __shared__ float st[128 * 64];
    __shared__ float o2[128 * 10];
    __shared__ float sc1[64], sh1[64], sc2[10], sh2[10];
    int tid = threadIdx.x;
    for (int t = tid; t < 8192; t += 128) st[t] = g_tmp[t];
    __syncthreads();
    if (tid < 64) {
        float S = 0.f, Q = 0.f;
        for (int gr = 0; gr < 128; gr++) { float v = st[gr * 64 + tid]; S += v; Q += v * v; }
        float mu = S * (1.f / 128.f), var = Q * (1.f / 128.f) - mu * mu;
        float sc = blg[tid] * rsqrtf(var + 1e-5f);
        sc1[tid] = sc;
        sh1[tid] = blbt[tid] - mu * sc;
    }
    __syncthreads();
    for (int t = tid; t < 8192; t += 128) {
        int c = t & 63;
        st[t] = st[t] * sc1[c] + sh1[c];
    }
    __syncthreads();
    if (out_hh) for (int t = tid; t < 8192; t += 128) out_hh[t] = st[t];

    for (int t = tid; t < 1280; t += 128) {
        int gr = t / 10, j = t % 10;
        float a = llb[j];
#pragma unroll
        for (int k = 0; k < 64; k++) a = fmaf(st[gr * 64 + k], llW[k * 10 + j], a);
        o2[t] = fmaxf(a, 0.f);
    }
    __syncthreads();
    if (tid < 10) {
        float S = 0.f, Q = 0.f;
        for (int gr = 0; gr < 128; gr++) { float v = o2[gr * 10 + tid]; S += v; Q += v * v; }
        float mu = S * (1.f / 128.f), var = Q * (1.f / 128.f) - mu * mu;
        float sc = llg[tid] * rsqrtf(var + 1e-5f);
        sc2[tid] = sc;
        sh2[tid] = llbt[tid] - mu * sc;
    }
    __syncthreads();
    if (tid < 128 && out_lg) {
        float y[10];
        float mx = __int_as_float(0xff800000);
        for (int j = 0; j < 10; j++) {
            y[j] = o2[tid * 10 + j] * sc2[j] + sh2[j];
            mx = fmaxf(mx, y[j]);
        }
        float se = 0.f;
        for (int j = 0; j < 10; j++) se += expf(y[j] - mx);
        float lse = mx + logf(se);
        for (int j = 0; j < 10; j++) out_lg[tid * 10 + j] = y[j] - lse;
    }
}

// ============================ host ============================
extern "C" void kernel_launch(void* const* d_in, const int* in_sizes, int n_in,
                              void* d_out, int out_size)
{
    const float* feat = (const float*)d_in[0];
    const float* Wsrc = (const float*)d_in[1];
    const float* bsrc = (const float*)d_in[2];
    const float* Wdst = (const float*)d_in[3];
    const float* bdst = (const float*)d_in[4];
    const float* attn = (const float*)d_in[5];
    const float* bng  = (const float*)d_in[6];
    const float* bnb  = (const float*)d_in[7];
    const float* lpW  = (const float*)d_in[8];
    const float* lpb  = (const float*)d_in[9];
    const float* lpg  = (const float*)d_in[10];
    const float* lpbt = (const float*)d_in[11];
    const float* blW  = (const float*)d_in[12];
    const float* blb  = (const float*)d_in[13];
    const float* blg  = (const float*)d_in[14];
    const float* blbt = (const float*)d_in[15];
    const float* llW  = (const float*)d_in[16];
    const float* llb  = (const float*)d_in[17];
    const float* llg  = (const float*)d_in[18];
    const float* llbt = (const float*)d_in[19];
    const int* src = (const int*)d_in[20];
    const int* dst = (const int*)d_in[21];
    const int* gid = (const int*)d_in[22];

    int N = in_sizes[0] / 64;
    int E = in_sizes[20];
    int nb = (N + 1023) / 1024;

    void* p;
    cudaGetSymbolAddress(&p, g_hpre);
    const float* hpre_p = (const float*)p;
    cudaGetSymbolAddress(&p, g_deg);
    int* deg_p = (int*)p;

    static int attr_set = 0;
    if (!attr_set) {   // host-side, idempotent, no allocation
        cudaFuncSetAttribute(k_gemm, cudaFuncAttributePreferredSharedMemoryCarveout, 100);
        attr_set = 1;
    }

    cudaMemsetAsync(deg_p, 0, N * sizeof(int));

    dim3 gg((N + 127) / 128, 8);

    // my launch idx: 0 hist, 1 scan1, 2 scan23, 3 gemm(L0) <-- profiled, 4 scatter, 5 aggr(L0)
    k_hist<<<(E + 255) / 256, 256>>>(dst, E);
    k_scan1<<<nb, 1024>>>(N);
    k_scan23<<<nb, 1024>>>(N, E, nb);
    k_gemm<<<gg, 256>>>(feat, Wsrc, Wdst, bsrc, bdst, N, 0);
    k_scatter<<<(E + 255) / 256, 256>>>(src, dst, E);
    k_aggr<<<(N + 7) / 8, 256>>>(attn, N);

    k_gptr<<<(N + 255) / 256, 256>>>(gid, N);
    k_pool<<<NG, 256>>>();
    k_bnfin<<<1, 256>>>(bng, bnb, 1.0f / (float)N);
    k_poolmlp<<<1, 512>>>(lpW, lpb, lpg, lpbt, 0);

    for (int i = 1; i < 3; i++) {
        k_gemm<<<gg, 256>>>(hpre_p, Wsrc + (size_t)i * 64 * 256, Wdst + (size_t)i * 64 * 256,
                            bsrc + i * 256, bdst + i * 256, N, 1);
        k_aggr<<<(N + 7) / 8, 256>>>(attn + i * 256, N);
        k_pool<<<NG, 256>>>();
        k_bnfin<<<1, 256>>>(bng + i * 64, bnb + i * 64, 1.0f / (float)N);
        k_poolmlp<<<1, 512>>>(lpW + (size_t)i * 64 * 64, lpb + i * 64, lpg + i * 64, lpbt + i * 64, i);
    }

    k_final1<<<128, 64>>>(blW, blb);

    float* out = (float*)d_out;
    float* out_lg = nullptr;
    float* out_hh = nullptr;
    if (out_size >= 9472)      { out_lg = out; out_hh = out + 1280; }
    else if (out_size == 1280) { out_lg = out; }
    else                       { out_hh = out; }
    k_final2<<<1, 128>>>(blg, blbt, llW, llb, llg, llbt, out_lg, out_hh);
}